// round 5
// baseline (speedup 1.0000x reference)
#include <cuda_runtime.h>
#include <math.h>

// Problem constants
#define T_TOK 32768      // 8 * 4096 tokens
#define HDIM  1024
#define NEXP  64
#define TOPK  8
#define NB    8
#define SEQ   4096
#define TILE  64         // tokens per CTA
#define KT    64         // k-tile width (smem staging)
#define KC    256        // k-panel width (accumulator restart) — FROZEN numerics

// Per-(batch, expert) accumulators for aux loss + counts.
__device__ int   g_cnt [NB * NEXP];
__device__ float g_ssum[NB * NEXP];

__global__ void zero_kernel() {
    int i = threadIdx.x;
    if (i < NB * NEXP) { g_cnt[i] = 0; g_ssum[i] = 0.0f; }
}

// One CTA: 64 tokens x 64 experts. fp32 FMA GEMM, sequential-k per output with
// accumulator restart every KC=256 (matches reference rounding — do not change).
// Vectorized LDS.128 smem with XOR swizzle, register-prefetch global pipeline,
// parallel softmax epilogue (fp64 exp), top-8, renorm, histogram, column-sums.
__global__ __launch_bounds__(256) void gate_kernel(
    const float* __restrict__ hs,   // [T_TOK, HDIM]
    const float* __restrict__ w,    // [NEXP, HDIM]
    float* __restrict__ out)        // flat f32: [idx | weights | aux | counts]
{
    __shared__ float a_s[TILE * KT];       // token tile, swizzled, stride 64
    __shared__ float b_s[NEXP * KT];       // weight tile, swizzled
    __shared__ float s_p[TILE][NEXP + 1];  // logits -> probs
    __shared__ float s_mx[4][TILE];        // partial maxima
    __shared__ int   s_hist[NEXP];

    const int tid   = threadIdx.x;
    const int tBase = blockIdx.x * TILE;
    const int b     = blockIdx.x >> 6;     // 64 CTAs per batch

    if (tid < NEXP) s_hist[tid] = 0;

    float acc[4][4];   // current k-panel accumulator
    float tot[4][4];   // in-order sum of completed panels
#pragma unroll
    for (int i = 0; i < 4; ++i)
#pragma unroll
        for (int j = 0; j < 4; ++j) { acc[i][j] = 0.0f; tot[i][j] = 0.0f; }

    const int r0 = (tid >> 4) * 4;   // token sub-tile base
    const int c0 = (tid & 15) * 4;   // expert sub-tile base
    const int sA = ((r0 >> 2) & 7) << 2;   // shared swizzle for the 4 A rows
    const int sB = ((c0 >> 2) & 7) << 2;   // shared swizzle for the 4 B rows

    // Per-thread loader slots (4 float4 per array per tile), constant across kk.
    int lrow[4], soff[4];
    size_t gA[4], gB[4];
#pragma unroll
    for (int t = 0; t < 4; ++t) {
        int idx = tid + t * 256;          // 0..1023
        int row = idx >> 4;               // 0..63
        int c4  = (idx & 15) << 2;        // 0..60
        lrow[t] = row;
        soff[t] = row * KT + (c4 ^ (((row >> 2) & 7) << 2));
        gA[t] = (size_t)(tBase + row) * HDIM + c4;
        gB[t] = (size_t)row * HDIM + c4;
    }

    // Prefetch tile 0 into registers.
    float4 pa[4], pb[4];
#pragma unroll
    for (int t = 0; t < 4; ++t) {
        pa[t] = *reinterpret_cast<const float4*>(hs + gA[t]);
        pb[t] = *reinterpret_cast<const float4*>(w  + gB[t]);
    }

    for (int kk = 0; kk < HDIM; kk += KT) {
        // Commit prefetched tile to swizzled smem.
#pragma unroll
        for (int t = 0; t < 4; ++t) {
            *reinterpret_cast<float4*>(a_s + soff[t]) = pa[t];
            *reinterpret_cast<float4*>(b_s + soff[t]) = pb[t];
        }
        __syncthreads();

        // Kick off next tile's global loads (overlap with FFMA below).
        if (kk + KT < HDIM) {
#pragma unroll
            for (int t = 0; t < 4; ++t) {
                pa[t] = *reinterpret_cast<const float4*>(hs + gA[t] + kk + KT);
                pb[t] = *reinterpret_cast<const float4*>(w  + gB[t] + kk + KT);
            }
        }

        // 64 k-steps, unrolled by 4 with LDS.128. FMA order per accumulator
        // remains strictly k-ascending (numerics frozen).
#pragma unroll
        for (int k4 = 0; k4 < KT; k4 += 4) {
            const int ka = k4 ^ sA;
            const int kb = k4 ^ sB;
            float4 a0 = *reinterpret_cast<const float4*>(a_s + (r0 + 0) * KT + ka);
            float4 a1 = *reinterpret_cast<const float4*>(a_s + (r0 + 1) * KT + ka);
            float4 a2 = *reinterpret_cast<const float4*>(a_s + (r0 + 2) * KT + ka);
            float4 a3 = *reinterpret_cast<const float4*>(a_s + (r0 + 3) * KT + ka);
            float4 b0 = *reinterpret_cast<const float4*>(b_s + (c0 + 0) * KT + kb);
            float4 b1 = *reinterpret_cast<const float4*>(b_s + (c0 + 1) * KT + kb);
            float4 b2 = *reinterpret_cast<const float4*>(b_s + (c0 + 2) * KT + kb);
            float4 b3 = *reinterpret_cast<const float4*>(b_s + (c0 + 3) * KT + kb);
#define STEP(u) \
            acc[0][0] = fmaf(a0.u, b0.u, acc[0][0]); acc[0][1] = fmaf(a0.u, b1.u, acc[0][1]); \
            acc[0][2] = fmaf(a0.u, b2.u, acc[0][2]); acc[0][3] = fmaf(a0.u, b3.u, acc[0][3]); \
            acc[1][0] = fmaf(a1.u, b0.u, acc[1][0]); acc[1][1] = fmaf(a1.u, b1.u, acc[1][1]); \
            acc[1][2] = fmaf(a1.u, b2.u, acc[1][2]); acc[1][3] = fmaf(a1.u, b3.u, acc[1][3]); \
            acc[2][0] = fmaf(a2.u, b0.u, acc[2][0]); acc[2][1] = fmaf(a2.u, b1.u, acc[2][1]); \
            acc[2][2] = fmaf(a2.u, b2.u, acc[2][2]); acc[2][3] = fmaf(a2.u, b3.u, acc[2][3]); \
            acc[3][0] = fmaf(a3.u, b0.u, acc[3][0]); acc[3][1] = fmaf(a3.u, b1.u, acc[3][1]); \
            acc[3][2] = fmaf(a3.u, b2.u, acc[3][2]); acc[3][3] = fmaf(a3.u, b3.u, acc[3][3]);
            STEP(x) STEP(y) STEP(z) STEP(w)
#undef STEP
        }

        // End of a KC-panel: fold panel sum into total in order, restart.
        if (((kk + KT) & (KC - 1)) == 0) {
#pragma unroll
            for (int i = 0; i < 4; ++i)
#pragma unroll
                for (int j = 0; j < 4; ++j) {
                    tot[i][j] += acc[i][j];
                    acc[i][j] = 0.0f;
                }
        }
        __syncthreads();
    }

#pragma unroll
    for (int i = 0; i < 4; ++i)
#pragma unroll
        for (int j = 0; j < 4; ++j)
            s_p[r0 + i][c0 + j] = tot[i][j];
    __syncthreads();

    // ---- Epilogue: softmax (parallel max/exp), top-8, renorm, histogram ----
    const int et = tid & 63;     // token
    const int eq = tid >> 6;     // quarter (16 experts)
    {
        float m = -1e30f;
#pragma unroll
        for (int e = eq * 16; e < eq * 16 + 16; ++e) m = fmaxf(m, s_p[et][e]);
        s_mx[eq][et] = m;
    }
    __syncthreads();
    {
        // full max broadcast via recompute (cheap, deterministic)
        float m = fmaxf(fmaxf(s_mx[0][et], s_mx[1][et]),
                        fmaxf(s_mx[2][et], s_mx[3][et]));
        // exp in fp64 -> correctly-rounded fp32 scores (matches ref exp)
#pragma unroll
        for (int e = eq * 16; e < eq * 16 + 16; ++e)
            s_p[et][e] = (float)exp((double)(s_p[et][e] - m));
    }
    __syncthreads();

    if (tid < TILE) {
        const int t = tid;
        float sum = 0.0f;
#pragma unroll 8
        for (int e = 0; e < NEXP; ++e) sum += s_p[t][e];   // in index order
        float inv = (float)(1.0 / (double)sum);
#pragma unroll 8
        for (int e = 0; e < NEXP; ++e) s_p[t][e] *= inv;

        // top-8, descending, lowest index first on exact ties (lax.top_k)
        int   idx[TOPK];
        float wk [TOPK];
        float wsum = 0.0f;
#pragma unroll
        for (int s = 0; s < TOPK; ++s) {
            float best = -1.0f; int bi = 0;
            for (int e = 0; e < NEXP; ++e) {
                float v = s_p[t][e];
                if (v > best) { best = v; bi = e; }
            }
            idx[s] = bi; wk[s] = best; wsum += best;
            s_p[t][bi] = -1.0f;
        }
#pragma unroll
        for (int s = 0; s < TOPK; ++s) s_p[t][idx[s]] = wk[s];  // restore

        float inv2 = (float)(1.0 / ((double)wsum + 1e-20));
        size_t gt = (size_t)tBase + t;
#pragma unroll
        for (int s = 0; s < TOPK; ++s) {
            out[gt * TOPK + s] = (float)idx[s];
            out[(size_t)T_TOK * TOPK + gt * TOPK + s] = wk[s] * inv2;
            atomicAdd(&s_hist[idx[s]], 1);
        }
    }
    __syncthreads();

    if (tid < NEXP) {
        const int e = tid;
        float cs = 0.0f;
        for (int t2 = 0; t2 < TILE; ++t2) cs += s_p[t2][e];
        atomicAdd(&g_ssum[b * NEXP + e], cs);
        atomicAdd(&g_cnt [b * NEXP + e], s_hist[e]);
    }
}

// aux = ALPHA * mean_b sum_e [cnt(b,e) * NEXP/(SEQ*TOPK)] * [ssum(b,e)/SEQ]
__global__ void final_kernel(float* __restrict__ out) {
    __shared__ float red[NEXP];
    int e = threadIdx.x;          // 64 threads
    int c = 0; float partial = 0.0f;
#pragma unroll
    for (int b = 0; b < NB; ++b) {
        int cb = g_cnt[b * NEXP + e];
        c += cb;
        partial += (float)cb * g_ssum[b * NEXP + e];
    }
    out[(size_t)T_TOK * 2 * TOPK + 1 + e] = (float)c;  // expert_counts
    red[e] = partial;
    __syncthreads();
    if (e == 0) {
        float s = 0.0f;
        for (int i = 0; i < NEXP; ++i) s += red[i];
        float aux = 0.01f * ((float)NEXP / (float)(SEQ * TOPK))
                          * (1.0f / (float)SEQ) * (1.0f / (float)NB) * s;
        out[(size_t)T_TOK * 2 * TOPK] = aux;           // aux_loss
    }
}

extern "C" void kernel_launch(void* const* d_in, const int* in_sizes, int n_in,
                              void* d_out, int out_size) {
    const float* hs = (const float*)d_in[0];   // hidden_states [8,4096,1024] f32
    const float* w  = (const float*)d_in[1];   // weight [64,1024] f32
    float* out = (float*)d_out;

    zero_kernel <<<1, 512>>>();
    gate_kernel <<<T_TOK / TILE, 256>>>(hs, w, out);
    final_kernel<<<1, NEXP>>>(out);
}

// round 11
// speedup vs baseline: 1.7699x; 1.7699x over previous
#include <cuda_runtime.h>
#include <stdint.h>
#include <math.h>

// Problem constants
#define T_TOK 32768      // 8 * 4096 tokens
#define HDIM  1024
#define NEXP  64
#define TOPK  8
#define NB    8
#define SEQ   4096
#define TILE  64         // tokens per CTA
#define KT    64         // k-tile width (smem staging)
#define KC    256        // k-panel width (accumulator restart) — FROZEN numerics
#define ASZ   (TILE * KT)   // floats per A stage
#define BSZ   (NEXP * KT)   // floats per B stage

// Per-(batch, expert) accumulators for aux loss + counts.
__device__ int   g_cnt [NB * NEXP];
__device__ float g_ssum[NB * NEXP];

__global__ void zero_kernel() {
    int i = threadIdx.x;
    if (i < NB * NEXP) { g_cnt[i] = 0; g_ssum[i] = 0.0f; }
}

__device__ __forceinline__ void cp16(unsigned int dst, const float* src) {
    asm volatile("cp.async.ca.shared.global [%0], [%1], 16;\n"
                 :: "r"(dst), "l"(src));
}
__device__ __forceinline__ void cp_commit() {
    asm volatile("cp.async.commit_group;\n");
}

// One CTA: 64 tokens x 64 experts. fp32 FMA GEMM, sequential-k per output with
// accumulator restart every KC=256 (matches reference rounding — FROZEN).
// cp.async double-buffered smem, swizzled LDS.128 operand reads, unroll-4
// inner loop, parallel softmax epilogue (fp64 exp), top-8, renorm, histogram.
__global__ __launch_bounds__(256) void gate_kernel(
    const float* __restrict__ hs,   // [T_TOK, HDIM]
    const float* __restrict__ w,    // [NEXP, HDIM]
    float* __restrict__ out)        // flat f32: [idx | weights | aux | counts]
{
    __shared__ float a_s[2][ASZ];          // token tiles, swizzled, stride 64
    __shared__ float b_s[2][BSZ];          // weight tiles, swizzled
    __shared__ float s_p[TILE][NEXP + 1];  // logits -> probs
    __shared__ float s_mx[4][TILE];        // partial maxima
    __shared__ int   s_hist[NEXP];

    const int tid   = threadIdx.x;
    const int tBase = blockIdx.x * TILE;
    const int b     = blockIdx.x >> 6;     // 64 CTAs per batch

    if (tid < NEXP) s_hist[tid] = 0;

    float acc[4][4];   // current k-panel accumulator
    float tot[4][4];   // in-order sum of completed panels
#pragma unroll
    for (int i = 0; i < 4; ++i)
#pragma unroll
        for (int j = 0; j < 4; ++j) { acc[i][j] = 0.0f; tot[i][j] = 0.0f; }

    const int r0 = (tid >> 4) * 4;         // token sub-tile base
    const int c0 = (tid & 15) * 4;         // expert sub-tile base
    const int sA = ((r0 >> 2) & 7) << 2;   // swizzle for this thread's A rows
    const int sB = ((c0 >> 2) & 7) << 2;   // swizzle for this thread's B rows

    // Loader slots: 4 float4 per array per tile (1024 float4 / 256 threads).
    int soff[4], goff[4];                  // smem offset, global row*HDIM + c4
#pragma unroll
    for (int t = 0; t < 4; ++t) {
        int idx = tid + t * 256;           // 0..1023
        int row = idx >> 4;                // 0..63
        int c4  = (idx & 15) << 2;         // 0..60
        soff[t] = row * KT + (c4 ^ (((row >> 2) & 7) << 2));
        goff[t] = row * HDIM + c4;
    }

    unsigned int aBase = (unsigned int)__cvta_generic_to_shared(&a_s[0][0]);
    unsigned int bBase = (unsigned int)__cvta_generic_to_shared(&b_s[0][0]);

    // Prologue: async-load tile 0 into stage 0.
#pragma unroll
    for (int t = 0; t < 4; ++t) {
        cp16(aBase + 4 * soff[t], hs + (size_t)tBase * HDIM + goff[t]);
        cp16(bBase + 4 * soff[t], w  + goff[t]);
    }
    cp_commit();

    const int NT = HDIM / KT;              // 16 tiles
    for (int tt = 0; tt < NT; ++tt) {
        const int st = tt & 1;
        // Issue next tile into the other stage.
        if (tt + 1 < NT) {
            const int ns = (tt + 1) & 1;
            const int kn = (tt + 1) * KT;
#pragma unroll
            for (int t = 0; t < 4; ++t) {
                cp16(aBase + 4 * (ns * ASZ + soff[t]),
                     hs + (size_t)tBase * HDIM + goff[t] + kn);
                cp16(bBase + 4 * (ns * BSZ + soff[t]),
                     w  + goff[t] + kn);
            }
            cp_commit();
            asm volatile("cp.async.wait_group 1;\n");
        } else {
            asm volatile("cp.async.wait_group 0;\n");
        }
        __syncthreads();

        const float* aS = a_s[st];
        const float* bS = b_s[st];

        // 64 k-steps: LDS.128 along k, unroll 4 (fits L0 I$). FMA order per
        // accumulator strictly k-ascending — numerics FROZEN.
#pragma unroll 4
        for (int k4 = 0; k4 < KT; k4 += 4) {
            const int ka = k4 ^ sA;
            const int kb = k4 ^ sB;
            float4 a0 = *reinterpret_cast<const float4*>(aS + (r0 + 0) * KT + ka);
            float4 a1 = *reinterpret_cast<const float4*>(aS + (r0 + 1) * KT + ka);
            float4 a2 = *reinterpret_cast<const float4*>(aS + (r0 + 2) * KT + ka);
            float4 a3 = *reinterpret_cast<const float4*>(aS + (r0 + 3) * KT + ka);
            float4 b0 = *reinterpret_cast<const float4*>(bS + (c0 + 0) * KT + kb);
            float4 b1 = *reinterpret_cast<const float4*>(bS + (c0 + 1) * KT + kb);
            float4 b2 = *reinterpret_cast<const float4*>(bS + (c0 + 2) * KT + kb);
            float4 b3 = *reinterpret_cast<const float4*>(bS + (c0 + 3) * KT + kb);
#define STEP(u) \
            acc[0][0] = fmaf(a0.u, b0.u, acc[0][0]); acc[0][1] = fmaf(a0.u, b1.u, acc[0][1]); \
            acc[0][2] = fmaf(a0.u, b2.u, acc[0][2]); acc[0][3] = fmaf(a0.u, b3.u, acc[0][3]); \
            acc[1][0] = fmaf(a1.u, b0.u, acc[1][0]); acc[1][1] = fmaf(a1.u, b1.u, acc[1][1]); \
            acc[1][2] = fmaf(a1.u, b2.u, acc[1][2]); acc[1][3] = fmaf(a1.u, b3.u, acc[1][3]); \
            acc[2][0] = fmaf(a2.u, b0.u, acc[2][0]); acc[2][1] = fmaf(a2.u, b1.u, acc[2][1]); \
            acc[2][2] = fmaf(a2.u, b2.u, acc[2][2]); acc[2][3] = fmaf(a2.u, b3.u, acc[2][3]); \
            acc[3][0] = fmaf(a3.u, b0.u, acc[3][0]); acc[3][1] = fmaf(a3.u, b1.u, acc[3][1]); \
            acc[3][2] = fmaf(a3.u, b2.u, acc[3][2]); acc[3][3] = fmaf(a3.u, b3.u, acc[3][3]);
            STEP(x) STEP(y) STEP(z) STEP(w)
#undef STEP
        }

        // End of a KC-panel (every 4 tiles): fold into total in order, restart.
        if ((((tt + 1) * KT) & (KC - 1)) == 0) {
#pragma unroll
            for (int i = 0; i < 4; ++i)
#pragma unroll
                for (int j = 0; j < 4; ++j) {
                    tot[i][j] += acc[i][j];
                    acc[i][j] = 0.0f;
                }
        }
        __syncthreads();
    }

#pragma unroll
    for (int i = 0; i < 4; ++i)
#pragma unroll
        for (int j = 0; j < 4; ++j)
            s_p[r0 + i][c0 + j] = tot[i][j];
    __syncthreads();

    // ---- Epilogue (verified bit-identical in R5) ----
    const int et = tid & 63;     // token
    const int eq = tid >> 6;     // quarter (16 experts)
    {
        float m = -1e30f;
#pragma unroll
        for (int e = eq * 16; e < eq * 16 + 16; ++e) m = fmaxf(m, s_p[et][e]);
        s_mx[eq][et] = m;
    }
    __syncthreads();
    {
        float m = fmaxf(fmaxf(s_mx[0][et], s_mx[1][et]),
                        fmaxf(s_mx[2][et], s_mx[3][et]));
        // exp in fp64 -> correctly-rounded fp32 scores (FROZEN)
#pragma unroll
        for (int e = eq * 16; e < eq * 16 + 16; ++e)
            s_p[et][e] = (float)exp((double)(s_p[et][e] - m));
    }
    __syncthreads();

    if (tid < TILE) {
        const int t = tid;
        float sum = 0.0f;
#pragma unroll 8
        for (int e = 0; e < NEXP; ++e) sum += s_p[t][e];   // in index order
        float inv = (float)(1.0 / (double)sum);
#pragma unroll 8
        for (int e = 0; e < NEXP; ++e) s_p[t][e] *= inv;

        // top-8, descending, lowest index first on exact ties (lax.top_k)
        int   idx[TOPK];
        float wk [TOPK];
        float wsum = 0.0f;
#pragma unroll
        for (int s = 0; s < TOPK; ++s) {
            float best = -1.0f; int bi = 0;
            for (int e = 0; e < NEXP; ++e) {
                float v = s_p[t][e];
                if (v > best) { best = v; bi = e; }
            }
            idx[s] = bi; wk[s] = best; wsum += best;
            s_p[t][bi] = -1.0f;
        }
#pragma unroll
        for (int s = 0; s < TOPK; ++s) s_p[t][idx[s]] = wk[s];  // restore

        float inv2 = (float)(1.0 / ((double)wsum + 1e-20));
        size_t gt = (size_t)tBase + t;
#pragma unroll
        for (int s = 0; s < TOPK; ++s) {
            out[gt * TOPK + s] = (float)idx[s];
            out[(size_t)T_TOK * TOPK + gt * TOPK + s] = wk[s] * inv2;
            atomicAdd(&s_hist[idx[s]], 1);
        }
    }
    __syncthreads();

    if (tid < NEXP) {
        const int e = tid;
        float cs = 0.0f;
        for (int t2 = 0; t2 < TILE; ++t2) cs += s_p[t2][e];
        atomicAdd(&g_ssum[b * NEXP + e], cs);
        atomicAdd(&g_cnt [b * NEXP + e], s_hist[e]);
    }
}

// aux = ALPHA * mean_b sum_e [cnt(b,e) * NEXP/(SEQ*TOPK)] * [ssum(b,e)/SEQ]
__global__ void final_kernel(float* __restrict__ out) {
    __shared__ float red[NEXP];
    int e = threadIdx.x;          // 64 threads
    int c = 0; float partial = 0.0f;
#pragma unroll
    for (int b = 0; b < NB; ++b) {
        int cb = g_cnt[b * NEXP + e];
        c += cb;
        partial += (float)cb * g_ssum[b * NEXP + e];
    }
    out[(size_t)T_TOK * 2 * TOPK + 1 + e] = (float)c;  // expert_counts
    red[e] = partial;
    __syncthreads();
    if (e == 0) {
        float s = 0.0f;
        for (int i = 0; i < NEXP; ++i) s += red[i];
        float aux = 0.01f * ((float)NEXP / (float)(SEQ * TOPK))
                          * (1.0f / (float)SEQ) * (1.0f / (float)NB) * s;
        out[(size_t)T_TOK * 2 * TOPK] = aux;           // aux_loss
    }
}

extern "C" void kernel_launch(void* const* d_in, const int* in_sizes, int n_in,
                              void* d_out, int out_size) {
    const float* hs = (const float*)d_in[0];   // hidden_states [8,4096,1024] f32
    const float* w  = (const float*)d_in[1];   // weight [64,1024] f32
    float* out = (float*)d_out;

    zero_kernel <<<1, 512>>>();
    gate_kernel <<<T_TOK / TILE, 256>>>(hs, w, out);
    final_kernel<<<1, NEXP>>>(out);
}